// round 1
// baseline (speedup 1.0000x reference)
#include <cuda_runtime.h>
#include <math.h>

// Problem constants
#define OBS_C  128
#define MLPC   256
#define LMAXC  3
#define RFC    4
#define AFC    4
#define AANGC  3
#define NGRIDC 16
#define NRC    64
#define NPC    128
#define NHC    64
#define GC     64      // B * NACT = 2 * 32
#define NACTC  32
#define MC     7       // 2*AANG+1

#define TWO_PI_F 6.2831853071795864f
#define PI_F     3.1415926535897932f

// ---------------- device scratch (no allocations allowed) ----------------
__device__ float g_x0[2][GC * MLPC];          // scalar (m=0) channel state
__device__ float g_xl[2][GC * MLPC * 6];      // (g, c, l, comp) state
__device__ float g_c1[GC * NRC * 28];         // (g, r, k, m) radial-contracted coeffs

// ---------------- helpers ----------------
__device__ __forceinline__ float elu1(float x) {
    return x > 0.f ? x : expm1f(x);
}

// Fourier-grid pointwise nonlinearity: project to 16 grid pts, ELU, project back.
__device__ __forceinline__ void fourier_elu(
    float y0, const float yc[3], const float ys[3],
    const float* __restrict__ sBc, const float* __restrict__ sBs,
    float& z0, float zc[3], float zs[3])
{
    z0 = 0.f;
    zc[0] = zc[1] = zc[2] = 0.f;
    zs[0] = zs[1] = zs[2] = 0.f;
#pragma unroll
    for (int j = 0; j < NGRIDC; j++) {
        float c0 = sBc[j * 3 + 0], c1v = sBc[j * 3 + 1], c2v = sBc[j * 3 + 2];
        float s0 = sBs[j * 3 + 0], s1v = sBs[j * 3 + 1], s2v = sBs[j * 3 + 2];
        float v = y0
                + yc[0] * c0 + yc[1] * c1v + yc[2] * c2v
                + ys[0] * s0 + ys[1] * s1v + ys[2] * s2v;
        float w = elu1(v);
        z0 += w;
        zc[0] += w * c0;  zc[1] += w * c1v;  zc[2] += w * c2v;
        zs[0] += w * s0;  zs[1] += w * s1v;  zs[2] += w * s2v;
    }
    z0 *= (1.f / NGRIDC);
#pragma unroll
    for (int l = 0; l < 3; l++) {
        zc[l] *= (2.f / NGRIDC);
        zs[l] *= (2.f / NGRIDC);
    }
}

__device__ __forceinline__ void fill_fourier_tables(int tid, float* sBc, float* sBs) {
    if (tid < NGRIDC) {
        float th = (float)tid * (TWO_PI_F / NGRIDC);
#pragma unroll
        for (int l = 0; l < 3; l++) {
            float s, c;
            sincosf((float)(l + 1) * th, &s, &c);
            sBc[tid * 3 + l] = c;
            sBs[tid * 3 + l] = s;
        }
    }
}

// ---------------- kernel 1: input SO(2) layer + Fourier-ELU ----------------
// grid: 64 blocks (one per g), 256 threads (one per output channel)
__global__ __launch_bounds__(256) void k_layer1(
    const float* __restrict__ obs, const float* __restrict__ act,
    const float* __restrict__ W0, const float* __restrict__ b0,
    const float* __restrict__ AB)
{
    const int g = blockIdx.x, tid = threadIdx.x;
    __shared__ float sx0[OBS_C + 1];
    __shared__ float sxc[3][OBS_C];
    __shared__ float sxs[3][OBS_C];
    __shared__ float sBc[NGRIDC * 3], sBs[NGRIDC * 3];

    const float* orow = obs + (g / NACTC) * (OBS_C * MC);
    for (int idx = tid; idx < OBS_C * MC; idx += 256) {
        int c = idx / MC, t = idx % MC;
        float v = orow[idx];
        if (t == 0) sx0[c] = v;
        else {
            int l = (t - 1) >> 1, comp = (t - 1) & 1;
            if (comp) sxs[l][c] = v; else sxc[l][c] = v;
        }
    }
    if (tid == 0) sx0[OBS_C] = act[g];
    fill_fourier_tables(tid, sBc, sBs);
    __syncthreads();

    const int o = tid;
    float y0 = b0[o];
    {
        const float* w = W0 + o * (OBS_C + 1);
#pragma unroll 4
        for (int i = 0; i < OBS_C + 1; i++) y0 += w[i] * sx0[i];
    }
    float yc[3] = {0.f, 0.f, 0.f}, ys[3] = {0.f, 0.f, 0.f};
#pragma unroll
    for (int l = 0; l < 3; l++) {
        const float4* a4p = (const float4*)(AB + ((size_t)(l * 2 + 0) * MLPC + o) * OBS_C);
        const float4* b4p = (const float4*)(AB + ((size_t)(l * 2 + 1) * MLPC + o) * OBS_C);
        float ac = 0.f, as = 0.f;
        for (int i4 = 0; i4 < OBS_C / 4; i4++) {
            float4 a4 = a4p[i4];
            float4 b4 = b4p[i4];
            int i = i4 * 4;
            float xc0 = sxc[l][i], xc1 = sxc[l][i + 1], xc2 = sxc[l][i + 2], xc3 = sxc[l][i + 3];
            float xs0 = sxs[l][i], xs1 = sxs[l][i + 1], xs2 = sxs[l][i + 2], xs3 = sxs[l][i + 3];
            ac += a4.x * xc0 - b4.x * xs0;
            ac += a4.y * xc1 - b4.y * xs1;
            ac += a4.z * xc2 - b4.z * xs2;
            ac += a4.w * xc3 - b4.w * xs3;
            as += b4.x * xc0 + a4.x * xs0;
            as += b4.y * xc1 + a4.y * xs1;
            as += b4.z * xc2 + a4.z * xs2;
            as += b4.w * xc3 + a4.w * xs3;
        }
        yc[l] = ac; ys[l] = as;
    }

    float z0, zc[3], zs[3];
    fourier_elu(y0, yc, ys, sBc, sBs, z0, zc, zs);

    g_x0[0][g * MLPC + o] = z0;
    float* xo = g_xl[0] + (size_t)(g * MLPC + o) * 6;
#pragma unroll
    for (int l = 0; l < 3; l++) { xo[l * 2] = zc[l]; xo[l * 2 + 1] = zs[l]; }
}

// ---------------- kernel 2: hidden SO(2) layer + Fourier-ELU ----------------
// grid: (64, 2), 128 threads. block (g, half); each thread computes one output channel.
__global__ __launch_bounds__(128) void k_hidden(
    const float* __restrict__ W0h, const float* __restrict__ b0h,
    const float* __restrict__ ABh, int layer, int inb)
{
    const int g = blockIdx.x, half = blockIdx.y, tid = threadIdx.x;
    const int o = half * 128 + tid;
    __shared__ float sx0[MLPC];
    __shared__ float sxc[3][MLPC];
    __shared__ float sxs[3][MLPC];
    __shared__ float sBc[NGRIDC * 3], sBs[NGRIDC * 3];

    const float* x0p = g_x0[inb] + g * MLPC;
    const float* xlp = g_xl[inb] + (size_t)g * MLPC * 6;
    for (int c = tid; c < MLPC; c += 128) {
        sx0[c] = x0p[c];
#pragma unroll
        for (int l = 0; l < 3; l++) {
            sxc[l][c] = xlp[c * 6 + l * 2];
            sxs[l][c] = xlp[c * 6 + l * 2 + 1];
        }
    }
    fill_fourier_tables(tid, sBc, sBs);
    __syncthreads();

    const float* W = W0h + (size_t)layer * MLPC * MLPC + (size_t)o * MLPC;
    const float* ABbase = ABh + (size_t)layer * 6 * MLPC * MLPC;
    float y0 = b0h[layer * MLPC + o];
    float yc[3] = {0.f, 0.f, 0.f}, ys[3] = {0.f, 0.f, 0.f};

#pragma unroll 2
    for (int i = 0; i < MLPC; i += 4) {
        float4 w4 = *(const float4*)(W + i);
        y0 += w4.x * sx0[i] + w4.y * sx0[i + 1] + w4.z * sx0[i + 2] + w4.w * sx0[i + 3];
#pragma unroll
        for (int l = 0; l < 3; l++) {
            float4 a4 = *(const float4*)(ABbase + ((size_t)(l * 2 + 0) * MLPC + o) * MLPC + i);
            float4 b4 = *(const float4*)(ABbase + ((size_t)(l * 2 + 1) * MLPC + o) * MLPC + i);
            float xc0 = sxc[l][i], xc1 = sxc[l][i + 1], xc2 = sxc[l][i + 2], xc3 = sxc[l][i + 3];
            float xs0 = sxs[l][i], xs1 = sxs[l][i + 1], xs2 = sxs[l][i + 2], xs3 = sxs[l][i + 3];
            yc[l] += a4.x * xc0 - b4.x * xs0;
            yc[l] += a4.y * xc1 - b4.y * xs1;
            yc[l] += a4.z * xc2 - b4.z * xs2;
            yc[l] += a4.w * xc3 - b4.w * xs3;
            ys[l] += b4.x * xc0 + a4.x * xs0;
            ys[l] += b4.y * xc1 + a4.y * xs1;
            ys[l] += b4.z * xc2 + a4.z * xs2;
            ys[l] += b4.w * xc3 + a4.w * xs3;
        }
    }

    float z0, zc[3], zs[3];
    fourier_elu(y0, yc, ys, sBc, sBs, z0, zc, zs);

    int ob = inb ^ 1;
    g_x0[ob][g * MLPC + o] = z0;
    float* xo = g_xl[ob] + (size_t)(g * MLPC + o) * 6;
#pragma unroll
    for (int l = 0; l < 3; l++) { xo[l * 2] = zc[l]; xo[l * 2 + 1] = zs[l]; }
}

// ---------------- kernel 3: output SO(2) layer + radial contraction ----------------
// grid: 64 blocks (one per g), 256 threads = 16 outputs x 16 i-chunks
__global__ __launch_bounds__(256) void k_out(
    const float* __restrict__ Wout, const float* __restrict__ bout,
    const float* __restrict__ ABout, const float* __restrict__ rad, int inb)
{
    const int g = blockIdx.x, tid = threadIdx.x;
    __shared__ float sx0[MLPC];
    __shared__ float sxc[3][MLPC];
    __shared__ float sxs[3][MLPC];
    __shared__ float coeffs[16 * MC];

    const float* x0p = g_x0[inb] + g * MLPC;
    const float* xlp = g_xl[inb] + (size_t)g * MLPC * 6;
    {
        int c = tid;
        sx0[c] = x0p[c];
#pragma unroll
        for (int l = 0; l < 3; l++) {
            sxc[l][c] = xlp[c * 6 + l * 2];
            sxs[l][c] = xlp[c * 6 + l * 2 + 1];
        }
    }
    __syncthreads();

    const int o = tid >> 4, q = tid & 15;
    float acc[MC];
#pragma unroll
    for (int m = 0; m < MC; m++) acc[m] = 0.f;

    for (int i = q; i < MLPC; i += 16) {
        float x0v = sx0[i];
        acc[0] += Wout[o * MLPC + i] * x0v;
#pragma unroll
        for (int aa = 0; aa < 3; aa++) {
            float a = ABout[((size_t)(aa * 2 + 0) * 16 + o) * MLPC + i];
            float b = ABout[((size_t)(aa * 2 + 1) * 16 + o) * MLPC + i];
            float xc = sxc[aa][i], xs = sxs[aa][i];
            acc[1 + 2 * aa] += a * xc - b * xs;
            acc[2 + 2 * aa] += b * xc + a * xs;
        }
    }
#pragma unroll
    for (int m = 0; m < MC; m++) {
#pragma unroll
        for (int off = 8; off > 0; off >>= 1)
            acc[m] += __shfl_down_sync(0xffffffffu, acc[m], off, 16);
    }
    if (q == 0) {
        coeffs[o * MC + 0] = acc[0] + bout[o];
#pragma unroll
        for (int m = 1; m < MC; m++) coeffs[o * MC + m] = acc[m];
    }
    __syncthreads();

    // c1[g,k,m,r] = sum_n P[g,k,n,m] * rad[m,n,r],  P[g,k,n,m] = coeffs[n*4+k][m]
    const int k = tid >> 6, r = tid & 63;
    float* outp = g_c1 + ((size_t)(g * NRC + r)) * 28 + k * MC;
#pragma unroll
    for (int m = 0; m < MC; m++) {
        float s = 0.f;
#pragma unroll
        for (int n = 0; n < 4; n++)
            s += coeffs[(n * 4 + k) * MC + m] * rad[(m * 4 + n) * NRC + r];
        outp[m] = s;
    }
}

// ---------------- kernel 4: separable expansion (the HBM-write kernel) ----------------
// grid: G*NR = 4096 blocks (one per (g,r)), 256 threads.
__global__ __launch_bounds__(256) void k_expand(float* __restrict__ out)
{
    const int gr = blockIdx.x;         // g*NR + r
    const int tid = threadIdx.x;
    __shared__ float sc1[28];
    __shared__ float su[4 * NPC];      // u[k][p]

    if (tid < 28) sc1[tid] = g_c1[(size_t)gr * 28 + tid];

    // ax[k][h] for this thread's 4 h values (h fixed per thread across all iters)
    const int hgrp = tid & 15;
    float rax[4][4];
#pragma unroll
    for (int k = 0; k < 4; k++)
#pragma unroll
        for (int j = 0; j < 4; j++) {
            int h = hgrp * 4 + j;
            rax[k][j] = 1.4142135623730951f *
                        sinf((float)(k + 1) * PI_F * (float)h / (float)(NHC - 1));
        }
    __syncthreads();  // sc1 ready

    // u[k,p] = c1[k,0]/sqrt(2pi) + (1/sqrt(pi)) * sum_m (cos/sin terms)
    const float A0 = 0.3989422804014327f;       // 1/sqrt(2*pi)
    const float ISP = 0.5641895835477563f;      // 1/sqrt(pi)
#pragma unroll
    for (int idx = tid; idx < 512; idx += 256) {
        int k = idx >> 7, p = idx & 127;
        float phi = (float)p * (TWO_PI_F / NPC);
        float s1, c1v;
        sincosf(phi, &s1, &c1v);
        float c2v = c1v * c1v - s1 * s1;
        float s2  = 2.f * s1 * c1v;
        float c3v = c2v * c1v - s2 * s1;
        float s3  = s2 * c1v + c2v * s1;
        const float* c = sc1 + k * MC;
        su[idx] = c[0] * A0 + ISP * (c[1] * c1v + c[2] * s1 +
                                     c[3] * c2v + c[4] * s2 +
                                     c[5] * c3v + c[6] * s3);
    }
    __syncthreads();

    float4* ob = (float4*)out + (size_t)gr * (NPC * NHC / 4);
    const int pg = tid >> 4;    // 0..15
#pragma unroll
    for (int it = 0; it < 8; it++) {
        int p = it * 16 + pg;
        float u0 = su[p], u1 = su[NPC + p], u2 = su[2 * NPC + p], u3 = su[3 * NPC + p];
        float4 v;
        v.x = u0 * rax[0][0] + u1 * rax[1][0] + u2 * rax[2][0] + u3 * rax[3][0];
        v.y = u0 * rax[0][1] + u1 * rax[1][1] + u2 * rax[2][1] + u3 * rax[3][1];
        v.z = u0 * rax[0][2] + u1 * rax[1][2] + u2 * rax[2][2] + u3 * rax[3][2];
        v.w = u0 * rax[0][3] + u1 * rax[1][3] + u2 * rax[2][3] + u3 * rax[3][3];
        ob[p * 16 + hgrp] = v;
    }
}

// ---------------- launch ----------------
extern "C" void kernel_launch(void* const* d_in, const int* in_sizes, int n_in,
                              void* d_out, int out_size)
{
    const float* obs   = (const float*)d_in[0];
    const float* act   = (const float*)d_in[1];
    const float* W0_1  = (const float*)d_in[2];
    const float* b0_1  = (const float*)d_in[3];
    const float* AB1   = (const float*)d_in[4];
    const float* W0_h  = (const float*)d_in[5];
    const float* b0_h  = (const float*)d_in[6];
    const float* ABh   = (const float*)d_in[7];
    const float* Wout0 = (const float*)d_in[8];
    const float* bout0 = (const float*)d_in[9];
    const float* ABout = (const float*)d_in[10];
    const float* rad   = (const float*)d_in[11];

    k_layer1<<<GC, 256>>>(obs, act, W0_1, b0_1, AB1);
    k_hidden<<<dim3(GC, 2), 128>>>(W0_h, b0_h, ABh, 0, 0);
    k_hidden<<<dim3(GC, 2), 128>>>(W0_h, b0_h, ABh, 1, 1);
    k_out<<<GC, 256>>>(Wout0, bout0, ABout, rad, 0);
    k_expand<<<GC * NRC, 256>>>((float*)d_out);
}

// round 2
// speedup vs baseline: 2.9815x; 2.9815x over previous
#include <cuda_runtime.h>
#include <math.h>
#include <stdint.h>

#define OBS_C  128
#define MLPC   256
#define NGRIDC 16
#define NRC    64
#define NPC    128
#define NHC    64
#define GC     64
#define MC     7

#define TWO_PI_F 6.2831853071795864f
#define PI_F     3.1415926535897932f

// ---------------- device scratch ----------------
__device__ float g_c1[GC * NRC * 28];     // (g, r, k, m)

// ---------------- helpers ----------------
__device__ __forceinline__ uint32_t smem_u32(const void* p) {
    return (uint32_t)__cvta_generic_to_shared(p);
}

__device__ __forceinline__ void cluster_sync_() {
    asm volatile("barrier.cluster.arrive.aligned;" ::: "memory");
    asm volatile("barrier.cluster.wait.aligned;" ::: "memory");
}

__device__ __forceinline__ void st_remote(float* p, float v, int peer) {
    uint32_t la = smem_u32(p), ra;
    asm volatile("mapa.shared::cluster.u32 %0, %1, %2;" : "=r"(ra) : "r"(la), "r"(peer));
    asm volatile("st.shared::cluster.b32 [%0], %1;" :: "r"(ra), "r"(__float_as_uint(v)));
}

__device__ __forceinline__ float elu1(float x) { return x > 0.f ? x : expm1f(x); }

// ---------------- SO(2) GEMV: warp-per-output-pair, lane-split K ----------------
// W0 row r at W0 + r*w0s (w0s=K means aligned float4 rows; w0s=K+1 -> layer1 with
// extra act column). AB slab (l,comp) row r at AB + ((2l+comp)*ldO + r)*K.
// x buffers: x0[K], xc + l*256, xs + l*256 (contiguous K floats each).
// Outputs rows [oBase, oBase+nOut) written to y0/yc/ys at local index ol (stride 128).
template<bool AL, int NJ>
__device__ __forceinline__ void so2_gemv(
    const float* __restrict__ W0, int w0s,
    const float* __restrict__ bias,
    const float* __restrict__ AB, int ldO,
    const float* __restrict__ x0, const float* __restrict__ xc, const float* __restrict__ xs,
    float actv, int oBase, int nOut,
    float* __restrict__ y0, float* __restrict__ yc, float* __restrict__ ys)
{
    const int tid = threadIdx.x, lane = tid & 31, wid = tid >> 5;
    const int K = NJ * 128;

    for (int ol = wid * 2; ol < nOut; ol += 16) {
        const int rA = oBase + ol, rB = rA + 1;
        float aA[7], aB[7];
#pragma unroll
        for (int m = 0; m < 7; m++) { aA[m] = 0.f; aB[m] = 0.f; }

        const float* WA = W0 + (size_t)rA * w0s;
        const float* WB = W0 + (size_t)rB * w0s;

#pragma unroll
        for (int j = 0; j < NJ; j++) {
            const int i4 = lane + 32 * j;
            float4 v0 = ((const float4*)x0)[i4];
            if (AL) {
                float4 wA4 = ((const float4*)WA)[i4];
                float4 wB4 = ((const float4*)WB)[i4];
                aA[0] += wA4.x * v0.x + wA4.y * v0.y + wA4.z * v0.z + wA4.w * v0.w;
                aB[0] += wB4.x * v0.x + wB4.y * v0.y + wB4.z * v0.z + wB4.w * v0.w;
            } else {
                const float* wA = WA + 4 * i4;
                const float* wB = WB + 4 * i4;
                aA[0] += wA[0] * v0.x + wA[1] * v0.y + wA[2] * v0.z + wA[3] * v0.w;
                aB[0] += wB[0] * v0.x + wB[1] * v0.y + wB[2] * v0.z + wB[3] * v0.w;
            }
#pragma unroll
            for (int l = 0; l < 3; l++) {
                float4 vc = ((const float4*)(xc + l * 256))[i4];
                float4 vs = ((const float4*)(xs + l * 256))[i4];
                float4 a4 = ((const float4*)(AB + ((size_t)(2 * l) * ldO + rA) * K))[i4];
                float4 b4 = ((const float4*)(AB + ((size_t)(2 * l + 1) * ldO + rA) * K))[i4];
                aA[1 + 2 * l] += a4.x * vc.x - b4.x * vs.x;
                aA[1 + 2 * l] += a4.y * vc.y - b4.y * vs.y;
                aA[1 + 2 * l] += a4.z * vc.z - b4.z * vs.z;
                aA[1 + 2 * l] += a4.w * vc.w - b4.w * vs.w;
                aA[2 + 2 * l] += b4.x * vc.x + a4.x * vs.x;
                aA[2 + 2 * l] += b4.y * vc.y + a4.y * vs.y;
                aA[2 + 2 * l] += b4.z * vc.z + a4.z * vs.z;
                aA[2 + 2 * l] += b4.w * vc.w + a4.w * vs.w;
                float4 a4b = ((const float4*)(AB + ((size_t)(2 * l) * ldO + rB) * K))[i4];
                float4 b4b = ((const float4*)(AB + ((size_t)(2 * l + 1) * ldO + rB) * K))[i4];
                aB[1 + 2 * l] += a4b.x * vc.x - b4b.x * vs.x;
                aB[1 + 2 * l] += a4b.y * vc.y - b4b.y * vs.y;
                aB[1 + 2 * l] += a4b.z * vc.z - b4b.z * vs.z;
                aB[1 + 2 * l] += a4b.w * vc.w - b4b.w * vs.w;
                aB[2 + 2 * l] += b4b.x * vc.x + a4b.x * vs.x;
                aB[2 + 2 * l] += b4b.y * vc.y + a4b.y * vs.y;
                aB[2 + 2 * l] += b4b.z * vc.z + a4b.z * vs.z;
                aB[2 + 2 * l] += b4b.w * vc.w + a4b.w * vs.w;
            }
        }
#pragma unroll
        for (int off = 16; off > 0; off >>= 1) {
#pragma unroll
            for (int m = 0; m < 7; m++) {
                aA[m] += __shfl_xor_sync(0xffffffffu, aA[m], off);
                aB[m] += __shfl_xor_sync(0xffffffffu, aB[m], off);
            }
        }
        if (lane < 2) {
            const float* acc = lane ? aB : aA;
            const int r = lane ? rB : rA;
            const int olw = ol + lane;
            float extra = AL ? 0.f : W0[(size_t)r * w0s + K] * actv;
            y0[olw] = acc[0] + bias[r] + extra;
#pragma unroll
            for (int l = 0; l < 3; l++) {
                yc[l * 128 + olw] = acc[1 + 2 * l];
                ys[l * 128 + olw] = acc[2 + 2 * l];
            }
        }
    }
}

// ---------------- activation + DSMEM exchange ----------------
__device__ __forceinline__ void act_exchange(
    const float* __restrict__ sy0, const float* __restrict__ syc, const float* __restrict__ sys,
    const float* __restrict__ sBc, const float* __restrict__ sBs,
    float* __restrict__ nx0, float* __restrict__ nxc, float* __restrict__ nxs, int half)
{
    const int tid = threadIdx.x;
    if (tid < 128) {
        const int o = half * 128 + tid;
        float y0v = sy0[tid];
        float ycv[3], ysv[3];
#pragma unroll
        for (int l = 0; l < 3; l++) { ycv[l] = syc[l * 128 + tid]; ysv[l] = sys[l * 128 + tid]; }
        float z0 = 0.f, zc[3] = {0.f, 0.f, 0.f}, zs[3] = {0.f, 0.f, 0.f};
#pragma unroll
        for (int j = 0; j < NGRIDC; j++) {
            float c0 = sBc[j * 3], c1v = sBc[j * 3 + 1], c2v = sBc[j * 3 + 2];
            float s0 = sBs[j * 3], s1v = sBs[j * 3 + 1], s2v = sBs[j * 3 + 2];
            float v = y0v + ycv[0] * c0 + ycv[1] * c1v + ycv[2] * c2v
                          + ysv[0] * s0 + ysv[1] * s1v + ysv[2] * s2v;
            float w = elu1(v);
            z0 += w;
            zc[0] += w * c0;  zc[1] += w * c1v;  zc[2] += w * c2v;
            zs[0] += w * s0;  zs[1] += w * s1v;  zs[2] += w * s2v;
        }
        z0 *= (1.f / NGRIDC);
        const int peer = half ^ 1;
        nx0[o] = z0;
        st_remote(&nx0[o], z0, peer);
#pragma unroll
        for (int l = 0; l < 3; l++) {
            float c = zc[l] * (2.f / NGRIDC), s = zs[l] * (2.f / NGRIDC);
            nxc[l * 256 + o] = c;  st_remote(&nxc[l * 256 + o], c, peer);
            nxs[l * 256 + o] = s;  st_remote(&nxs[l * 256 + o], s, peer);
        }
    }
}

// ---------------- fused MLP kernel: one cluster of 2 CTAs per g ----------------
__global__ __launch_bounds__(256, 1) __cluster_dims__(2, 1, 1)
void k_mlp(const float* __restrict__ obs, const float* __restrict__ act,
           const float* __restrict__ W0_1, const float* __restrict__ b0_1,
           const float* __restrict__ AB1,
           const float* __restrict__ W0_h, const float* __restrict__ b0_h,
           const float* __restrict__ ABh,
           const float* __restrict__ Wout, const float* __restrict__ bout,
           const float* __restrict__ ABout, const float* __restrict__ rad)
{
    __shared__ float sb0[2][256];
    __shared__ float sbc[2][3 * 256];
    __shared__ float sbs[2][3 * 256];
    __shared__ float sy0[128], syc[3 * 128], sys[3 * 128];
    __shared__ float sBc[NGRIDC * 3], sBs[NGRIDC * 3];

    const int tid = threadIdx.x;
    const int g = blockIdx.x >> 1;
    const int half = blockIdx.x & 1;

    // load obs channels into layer-1 input buffers (buf 0)
    const float* orow = obs + (size_t)(g >> 5) * (OBS_C * MC);
    for (int idx = tid; idx < OBS_C * MC; idx += 256) {
        int c = idx / 7, t = idx - c * 7;
        float v = orow[idx];
        if (t == 0) sb0[0][c] = v;
        else {
            int l = (t - 1) >> 1;
            if ((t - 1) & 1) sbs[0][l * 256 + c] = v;
            else             sbc[0][l * 256 + c] = v;
        }
    }
    const float actv = act[g];
    if (tid < NGRIDC) {
        float th = (float)tid * (TWO_PI_F / NGRIDC);
#pragma unroll
        for (int l = 0; l < 3; l++) {
            float s, c;
            sincosf((float)(l + 1) * th, &s, &c);
            sBc[tid * 3 + l] = c;
            sBs[tid * 3 + l] = s;
        }
    }
    __syncthreads();

    // layer 1: K=128 (+act column), outputs half*128..+128
    so2_gemv<false, 1>(W0_1, OBS_C + 1, b0_1, AB1, 256,
                       sb0[0], sbc[0], sbs[0], actv, half * 128, 128, sy0, syc, sys);
    __syncthreads();
    act_exchange(sy0, syc, sys, sBc, sBs, sb0[1], sbc[1], sbs[1], half);
    cluster_sync_();

    // hidden layer 0: K=256
    so2_gemv<true, 2>(W0_h, 256, b0_h, ABh, 256,
                      sb0[1], sbc[1], sbs[1], 0.f, half * 128, 128, sy0, syc, sys);
    __syncthreads();
    act_exchange(sy0, syc, sys, sBc, sBs, sb0[0], sbc[0], sbs[0], half);
    cluster_sync_();

    // hidden layer 1
    so2_gemv<true, 2>(W0_h + 256 * 256, 256, b0_h + 256, ABh + 6 * 256 * 256, 256,
                      sb0[0], sbc[0], sbs[0], 0.f, half * 128, 128, sy0, syc, sys);
    __syncthreads();
    act_exchange(sy0, syc, sys, sBc, sBs, sb0[1], sbc[1], sbs[1], half);
    cluster_sync_();

    // output layer: 16 rows, computed redundantly by both CTAs (tiny)
    so2_gemv<true, 2>(Wout, 256, bout, ABout, 16,
                      sb0[1], sbc[1], sbs[1], 0.f, 0, 16, sy0, syc, sys);
    __syncthreads();

    // radial contraction: c1[g,r,k,m] ; this CTA covers r in [half*32, half*32+32)
    if (tid < 128) {
        const int k = tid >> 5, r = half * 32 + (tid & 31);
        float o7[MC];
#pragma unroll
        for (int m = 0; m < MC; m++) {
            float s = 0.f;
#pragma unroll
            for (int n = 0; n < 4; n++) {
                int o = n * 4 + k;
                float cv = (m == 0) ? sy0[o]
                          : ((m & 1) ? syc[((m - 1) >> 1) * 128 + o]
                                     : sys[((m >> 1) - 1) * 128 + o]);
                s += cv * rad[(m * 4 + n) * NRC + r];
            }
            o7[m] = s;
        }
        float* dst = g_c1 + ((size_t)(g * NRC + r)) * 28 + k * MC;
#pragma unroll
        for (int m = 0; m < MC; m++) dst[m] = o7[m];
    }
}

// ---------------- expansion kernel (HBM-write bound) ----------------
__global__ __launch_bounds__(256) void k_expand(float* __restrict__ out)
{
    const int gr = blockIdx.x;          // g*NR + r
    const int tid = threadIdx.x;
    __shared__ float sc1[28];
    __shared__ float su[4 * NPC];
    __shared__ float sax[4 * NHC];      // ax[k][h]

    if (tid < 28) sc1[tid] = g_c1[(size_t)gr * 28 + tid];
    {
        int k = tid >> 6, h = tid & 63;
        sax[tid] = 1.4142135623730951f *
                   sinf((float)(k + 1) * PI_F * (float)h * (1.f / (NHC - 1)));
    }
    __syncthreads();

    const float A0 = 0.3989422804014327f;   // 1/sqrt(2*pi)
    const float ISP = 0.5641895835477563f;  // 1/sqrt(pi)
#pragma unroll
    for (int idx = tid; idx < 512; idx += 256) {
        int k = idx >> 7, p = idx & 127;
        float phi = (float)p * (TWO_PI_F / NPC);
        float s1, c1v;
        sincosf(phi, &s1, &c1v);
        float c2v = c1v * c1v - s1 * s1;
        float s2  = 2.f * s1 * c1v;
        float c3v = c2v * c1v - s2 * s1;
        float s3  = s2 * c1v + c2v * s1;
        const float* c = sc1 + k * MC;
        su[idx] = c[0] * A0 + ISP * (c[1] * c1v + c[2] * s1 +
                                     c[3] * c2v + c[4] * s2 +
                                     c[5] * c3v + c[6] * s3);
    }
    const int hgrp = tid & 15;
    float rax[4][4];
#pragma unroll
    for (int k = 0; k < 4; k++)
#pragma unroll
        for (int j = 0; j < 4; j++)
            rax[k][j] = sax[k * NHC + hgrp * 4 + j];
    __syncthreads();

    float4* ob = (float4*)out + (size_t)gr * (NPC * NHC / 4);
    const int pg = tid >> 4;
#pragma unroll
    for (int it = 0; it < 8; it++) {
        int p = it * 16 + pg;
        float u0 = su[p], u1 = su[NPC + p], u2 = su[2 * NPC + p], u3 = su[3 * NPC + p];
        float4 v;
        v.x = u0 * rax[0][0] + u1 * rax[1][0] + u2 * rax[2][0] + u3 * rax[3][0];
        v.y = u0 * rax[0][1] + u1 * rax[1][1] + u2 * rax[2][1] + u3 * rax[3][1];
        v.z = u0 * rax[0][2] + u1 * rax[1][2] + u2 * rax[2][2] + u3 * rax[3][2];
        v.w = u0 * rax[0][3] + u1 * rax[1][3] + u2 * rax[2][3] + u3 * rax[3][3];
        __stcs(&ob[p * 16 + hgrp], v);
    }
}

// ---------------- launch ----------------
extern "C" void kernel_launch(void* const* d_in, const int* in_sizes, int n_in,
                              void* d_out, int out_size)
{
    const float* obs   = (const float*)d_in[0];
    const float* act   = (const float*)d_in[1];
    const float* W0_1  = (const float*)d_in[2];
    const float* b0_1  = (const float*)d_in[3];
    const float* AB1   = (const float*)d_in[4];
    const float* W0_h  = (const float*)d_in[5];
    const float* b0_h  = (const float*)d_in[6];
    const float* ABh   = (const float*)d_in[7];
    const float* Wout0 = (const float*)d_in[8];
    const float* bout0 = (const float*)d_in[9];
    const float* ABout = (const float*)d_in[10];
    const float* rad   = (const float*)d_in[11];

    k_mlp<<<2 * GC, 256>>>(obs, act, W0_1, b0_1, AB1, W0_h, b0_h, ABh,
                           Wout0, bout0, ABout, rad);
    k_expand<<<GC * NRC, 256>>>((float*)d_out);
}

// round 3
// speedup vs baseline: 2.9872x; 1.0019x over previous
#include <cuda_runtime.h>
#include <math.h>
#include <stdint.h>

#define OBS_C  128
#define MLPC   256
#define NGRIDC 16
#define NRC    64
#define NPC    128
#define NHC    64
#define GC     64
#define MC     7

#define TWO_PI_F 6.2831853071795864f
#define PI_F     3.1415926535897932f

// ---------------- device scratch ----------------
__device__ float g_c1[GC * NRC * 28];     // (g, r, k, m)

// ---------------- helpers ----------------
__device__ __forceinline__ uint32_t smem_u32(const void* p) {
    return (uint32_t)__cvta_generic_to_shared(p);
}

__device__ __forceinline__ void cluster_sync_() {
    asm volatile("barrier.cluster.arrive.aligned;" ::: "memory");
    asm volatile("barrier.cluster.wait.aligned;" ::: "memory");
}

__device__ __forceinline__ void st_remote(float* p, float v, int peer) {
    uint32_t la = smem_u32(p), ra;
    asm volatile("mapa.shared::cluster.u32 %0, %1, %2;" : "=r"(ra) : "r"(la), "r"(peer));
    asm volatile("st.shared::cluster.b32 [%0], %1;" :: "r"(ra), "r"(__float_as_uint(v)));
}

__device__ __forceinline__ float elu1(float x) { return x > 0.f ? x : expm1f(x); }

// ---------------- SO(2) GEMV: warp-per-output-pair, lane-split K ----------------
// W0 row r at W0 + r*w0s (w0s=K means aligned float4 rows; w0s=K+1 -> layer1 with
// extra act column). AB slab (l,comp) row r at AB + ((2l+comp)*ldO + r)*K.
// x buffers: x0[K], xc + l*256, xs + l*256 (contiguous K floats each).
// Outputs rows [oBase, oBase+nOut) written to y0/yc/ys at local index ol (stride 128).
template<bool AL, int NJ>
__device__ __forceinline__ void so2_gemv(
    const float* __restrict__ W0, int w0s,
    const float* __restrict__ bias,
    const float* __restrict__ AB, int ldO,
    const float* __restrict__ x0, const float* __restrict__ xc, const float* __restrict__ xs,
    float actv, int oBase, int nOut,
    float* __restrict__ y0, float* __restrict__ yc, float* __restrict__ ys)
{
    const int tid = threadIdx.x, lane = tid & 31, wid = tid >> 5;
    const int K = NJ * 128;

    for (int ol = wid * 2; ol < nOut; ol += 16) {
        const int rA = oBase + ol, rB = rA + 1;
        float aA[7], aB[7];
#pragma unroll
        for (int m = 0; m < 7; m++) { aA[m] = 0.f; aB[m] = 0.f; }

        const float* WA = W0 + (size_t)rA * w0s;
        const float* WB = W0 + (size_t)rB * w0s;

#pragma unroll
        for (int j = 0; j < NJ; j++) {
            const int i4 = lane + 32 * j;
            float4 v0 = ((const float4*)x0)[i4];
            if (AL) {
                float4 wA4 = ((const float4*)WA)[i4];
                float4 wB4 = ((const float4*)WB)[i4];
                aA[0] += wA4.x * v0.x + wA4.y * v0.y + wA4.z * v0.z + wA4.w * v0.w;
                aB[0] += wB4.x * v0.x + wB4.y * v0.y + wB4.z * v0.z + wB4.w * v0.w;
            } else {
                const float* wA = WA + 4 * i4;
                const float* wB = WB + 4 * i4;
                aA[0] += wA[0] * v0.x + wA[1] * v0.y + wA[2] * v0.z + wA[3] * v0.w;
                aB[0] += wB[0] * v0.x + wB[1] * v0.y + wB[2] * v0.z + wB[3] * v0.w;
            }
#pragma unroll
            for (int l = 0; l < 3; l++) {
                float4 vc = ((const float4*)(xc + l * 256))[i4];
                float4 vs = ((const float4*)(xs + l * 256))[i4];
                float4 a4 = ((const float4*)(AB + ((size_t)(2 * l) * ldO + rA) * K))[i4];
                float4 b4 = ((const float4*)(AB + ((size_t)(2 * l + 1) * ldO + rA) * K))[i4];
                aA[1 + 2 * l] += a4.x * vc.x - b4.x * vs.x;
                aA[1 + 2 * l] += a4.y * vc.y - b4.y * vs.y;
                aA[1 + 2 * l] += a4.z * vc.z - b4.z * vs.z;
                aA[1 + 2 * l] += a4.w * vc.w - b4.w * vs.w;
                aA[2 + 2 * l] += b4.x * vc.x + a4.x * vs.x;
                aA[2 + 2 * l] += b4.y * vc.y + a4.y * vs.y;
                aA[2 + 2 * l] += b4.z * vc.z + a4.z * vs.z;
                aA[2 + 2 * l] += b4.w * vc.w + a4.w * vs.w;
                float4 a4b = ((const float4*)(AB + ((size_t)(2 * l) * ldO + rB) * K))[i4];
                float4 b4b = ((const float4*)(AB + ((size_t)(2 * l + 1) * ldO + rB) * K))[i4];
                aB[1 + 2 * l] += a4b.x * vc.x - b4b.x * vs.x;
                aB[1 + 2 * l] += a4b.y * vc.y - b4b.y * vs.y;
                aB[1 + 2 * l] += a4b.z * vc.z - b4b.z * vs.z;
                aB[1 + 2 * l] += a4b.w * vc.w - b4b.w * vs.w;
                aB[2 + 2 * l] += b4b.x * vc.x + a4b.x * vs.x;
                aB[2 + 2 * l] += b4b.y * vc.y + a4b.y * vs.y;
                aB[2 + 2 * l] += b4b.z * vc.z + a4b.z * vs.z;
                aB[2 + 2 * l] += b4b.w * vc.w + a4b.w * vs.w;
            }
        }
#pragma unroll
        for (int off = 16; off > 0; off >>= 1) {
#pragma unroll
            for (int m = 0; m < 7; m++) {
                aA[m] += __shfl_xor_sync(0xffffffffu, aA[m], off);
                aB[m] += __shfl_xor_sync(0xffffffffu, aB[m], off);
            }
        }
        if (lane < 2) {
            const float* acc = lane ? aB : aA;
            const int r = lane ? rB : rA;
            const int olw = ol + lane;
            float extra = AL ? 0.f : W0[(size_t)r * w0s + K] * actv;
            y0[olw] = acc[0] + bias[r] + extra;
#pragma unroll
            for (int l = 0; l < 3; l++) {
                yc[l * 128 + olw] = acc[1 + 2 * l];
                ys[l * 128 + olw] = acc[2 + 2 * l];
            }
        }
    }
}

// ---------------- activation + DSMEM exchange ----------------
__device__ __forceinline__ void act_exchange(
    const float* __restrict__ sy0, const float* __restrict__ syc, const float* __restrict__ sys,
    const float* __restrict__ sBc, const float* __restrict__ sBs,
    float* __restrict__ nx0, float* __restrict__ nxc, float* __restrict__ nxs, int half)
{
    const int tid = threadIdx.x;
    if (tid < 128) {
        const int o = half * 128 + tid;
        float y0v = sy0[tid];
        float ycv[3], ysv[3];
#pragma unroll
        for (int l = 0; l < 3; l++) { ycv[l] = syc[l * 128 + tid]; ysv[l] = sys[l * 128 + tid]; }
        float z0 = 0.f, zc[3] = {0.f, 0.f, 0.f}, zs[3] = {0.f, 0.f, 0.f};
#pragma unroll
        for (int j = 0; j < NGRIDC; j++) {
            float c0 = sBc[j * 3], c1v = sBc[j * 3 + 1], c2v = sBc[j * 3 + 2];
            float s0 = sBs[j * 3], s1v = sBs[j * 3 + 1], s2v = sBs[j * 3 + 2];
            float v = y0v + ycv[0] * c0 + ycv[1] * c1v + ycv[2] * c2v
                          + ysv[0] * s0 + ysv[1] * s1v + ysv[2] * s2v;
            float w = elu1(v);
            z0 += w;
            zc[0] += w * c0;  zc[1] += w * c1v;  zc[2] += w * c2v;
            zs[0] += w * s0;  zs[1] += w * s1v;  zs[2] += w * s2v;
        }
        z0 *= (1.f / NGRIDC);
        const int peer = half ^ 1;
        nx0[o] = z0;
        st_remote(&nx0[o], z0, peer);
#pragma unroll
        for (int l = 0; l < 3; l++) {
            float c = zc[l] * (2.f / NGRIDC), s = zs[l] * (2.f / NGRIDC);
            nxc[l * 256 + o] = c;  st_remote(&nxc[l * 256 + o], c, peer);
            nxs[l * 256 + o] = s;  st_remote(&nxs[l * 256 + o], s, peer);
        }
    }
}

// ---------------- fused MLP kernel: one cluster of 2 CTAs per g ----------------
__global__ __launch_bounds__(256, 1) __cluster_dims__(2, 1, 1)
void k_mlp(const float* __restrict__ obs, const float* __restrict__ act,
           const float* __restrict__ W0_1, const float* __restrict__ b0_1,
           const float* __restrict__ AB1,
           const float* __restrict__ W0_h, const float* __restrict__ b0_h,
           const float* __restrict__ ABh,
           const float* __restrict__ Wout, const float* __restrict__ bout,
           const float* __restrict__ ABout, const float* __restrict__ rad)
{
    __shared__ float sb0[2][256];
    __shared__ float sbc[2][3 * 256];
    __shared__ float sbs[2][3 * 256];
    __shared__ float sy0[128], syc[3 * 128], sys[3 * 128];
    __shared__ float sBc[NGRIDC * 3], sBs[NGRIDC * 3];

    const int tid = threadIdx.x;
    const int g = blockIdx.x >> 1;
    const int half = blockIdx.x & 1;

    // load obs channels into layer-1 input buffers (buf 0)
    const float* orow = obs + (size_t)(g >> 5) * (OBS_C * MC);
    for (int idx = tid; idx < OBS_C * MC; idx += 256) {
        int c = idx / 7, t = idx - c * 7;
        float v = orow[idx];
        if (t == 0) sb0[0][c] = v;
        else {
            int l = (t - 1) >> 1;
            if ((t - 1) & 1) sbs[0][l * 256 + c] = v;
            else             sbc[0][l * 256 + c] = v;
        }
    }
    const float actv = act[g];
    if (tid < NGRIDC) {
        float th = (float)tid * (TWO_PI_F / NGRIDC);
#pragma unroll
        for (int l = 0; l < 3; l++) {
            float s, c;
            sincosf((float)(l + 1) * th, &s, &c);
            sBc[tid * 3 + l] = c;
            sBs[tid * 3 + l] = s;
        }
    }
    __syncthreads();

    // layer 1: K=128 (+act column), outputs half*128..+128
    so2_gemv<false, 1>(W0_1, OBS_C + 1, b0_1, AB1, 256,
                       sb0[0], sbc[0], sbs[0], actv, half * 128, 128, sy0, syc, sys);
    __syncthreads();
    act_exchange(sy0, syc, sys, sBc, sBs, sb0[1], sbc[1], sbs[1], half);
    cluster_sync_();

    // hidden layer 0: K=256
    so2_gemv<true, 2>(W0_h, 256, b0_h, ABh, 256,
                      sb0[1], sbc[1], sbs[1], 0.f, half * 128, 128, sy0, syc, sys);
    __syncthreads();
    act_exchange(sy0, syc, sys, sBc, sBs, sb0[0], sbc[0], sbs[0], half);
    cluster_sync_();

    // hidden layer 1
    so2_gemv<true, 2>(W0_h + 256 * 256, 256, b0_h + 256, ABh + 6 * 256 * 256, 256,
                      sb0[0], sbc[0], sbs[0], 0.f, half * 128, 128, sy0, syc, sys);
    __syncthreads();
    act_exchange(sy0, syc, sys, sBc, sBs, sb0[1], sbc[1], sbs[1], half);
    cluster_sync_();

    // output layer: 16 rows, computed redundantly by both CTAs (tiny)
    so2_gemv<true, 2>(Wout, 256, bout, ABout, 16,
                      sb0[1], sbc[1], sbs[1], 0.f, 0, 16, sy0, syc, sys);
    __syncthreads();

    // radial contraction: c1[g,r,k,m] ; this CTA covers r in [half*32, half*32+32)
    if (tid < 128) {
        const int k = tid >> 5, r = half * 32 + (tid & 31);
        float o7[MC];
#pragma unroll
        for (int m = 0; m < MC; m++) {
            float s = 0.f;
#pragma unroll
            for (int n = 0; n < 4; n++) {
                int o = n * 4 + k;
                float cv = (m == 0) ? sy0[o]
                          : ((m & 1) ? syc[((m - 1) >> 1) * 128 + o]
                                     : sys[((m >> 1) - 1) * 128 + o]);
                s += cv * rad[(m * 4 + n) * NRC + r];
            }
            o7[m] = s;
        }
        float* dst = g_c1 + ((size_t)(g * NRC + r)) * 28 + k * MC;
#pragma unroll
        for (int m = 0; m < MC; m++) dst[m] = o7[m];
    }
}

// ---------------- expansion kernel (HBM-write bound) ----------------
__global__ __launch_bounds__(256) void k_expand(float* __restrict__ out)
{
    const int gr = blockIdx.x;          // g*NR + r
    const int tid = threadIdx.x;
    __shared__ float sc1[28];
    __shared__ float su[4 * NPC];
    __shared__ float sax[4 * NHC];      // ax[k][h]

    if (tid < 28) sc1[tid] = g_c1[(size_t)gr * 28 + tid];
    {
        int k = tid >> 6, h = tid & 63;
        sax[tid] = 1.4142135623730951f *
                   sinf((float)(k + 1) * PI_F * (float)h * (1.f / (NHC - 1)));
    }
    __syncthreads();

    const float A0 = 0.3989422804014327f;   // 1/sqrt(2*pi)
    const float ISP = 0.5641895835477563f;  // 1/sqrt(pi)
#pragma unroll
    for (int idx = tid; idx < 512; idx += 256) {
        int k = idx >> 7, p = idx & 127;
        float phi = (float)p * (TWO_PI_F / NPC);
        float s1, c1v;
        sincosf(phi, &s1, &c1v);
        float c2v = c1v * c1v - s1 * s1;
        float s2  = 2.f * s1 * c1v;
        float c3v = c2v * c1v - s2 * s1;
        float s3  = s2 * c1v + c2v * s1;
        const float* c = sc1 + k * MC;
        su[idx] = c[0] * A0 + ISP * (c[1] * c1v + c[2] * s1 +
                                     c[3] * c2v + c[4] * s2 +
                                     c[5] * c3v + c[6] * s3);
    }
    const int hgrp = tid & 15;
    float rax[4][4];
#pragma unroll
    for (int k = 0; k < 4; k++)
#pragma unroll
        for (int j = 0; j < 4; j++)
            rax[k][j] = sax[k * NHC + hgrp * 4 + j];
    __syncthreads();

    float4* ob = (float4*)out + (size_t)gr * (NPC * NHC / 4);
    const int pg = tid >> 4;
#pragma unroll
    for (int it = 0; it < 8; it++) {
        int p = it * 16 + pg;
        float u0 = su[p], u1 = su[NPC + p], u2 = su[2 * NPC + p], u3 = su[3 * NPC + p];
        float4 v;
        v.x = u0 * rax[0][0] + u1 * rax[1][0] + u2 * rax[2][0] + u3 * rax[3][0];
        v.y = u0 * rax[0][1] + u1 * rax[1][1] + u2 * rax[2][1] + u3 * rax[3][1];
        v.z = u0 * rax[0][2] + u1 * rax[1][2] + u2 * rax[2][2] + u3 * rax[3][2];
        v.w = u0 * rax[0][3] + u1 * rax[1][3] + u2 * rax[2][3] + u3 * rax[3][3];
        __stcs(&ob[p * 16 + hgrp], v);
    }
}

// ---------------- launch ----------------
extern "C" void kernel_launch(void* const* d_in, const int* in_sizes, int n_in,
                              void* d_out, int out_size)
{
    const float* obs   = (const float*)d_in[0];
    const float* act   = (const float*)d_in[1];
    const float* W0_1  = (const float*)d_in[2];
    const float* b0_1  = (const float*)d_in[3];
    const float* AB1   = (const float*)d_in[4];
    const float* W0_h  = (const float*)d_in[5];
    const float* b0_h  = (const float*)d_in[6];
    const float* ABh   = (const float*)d_in[7];
    const float* Wout0 = (const float*)d_in[8];
    const float* bout0 = (const float*)d_in[9];
    const float* ABout = (const float*)d_in[10];
    const float* rad   = (const float*)d_in[11];

    k_mlp<<<2 * GC, 256>>>(obs, act, W0_1, b0_1, AB1, W0_h, b0_h, ABh,
                           Wout0, bout0, ABout, rad);
    k_expand<<<GC * NRC, 256>>>((float*)d_out);
}

// round 5
// speedup vs baseline: 3.0642x; 1.0258x over previous
#include <cuda_runtime.h>
#include <math.h>
#include <stdint.h>

#define OBS_C  128
#define MLPC   256
#define NGRIDC 16
#define NRC    64
#define NPC    128
#define NHC    64
#define GC     64
#define MC     7

#define XSTR   1792            // 7*256 floats per g
#define TWO_PI_F 6.2831853071795864f
#define PI_F     3.1415926535897932f

// ---------------- device scratch ----------------
__device__ __align__(16) float g_X[2][GC * XSTR];     // activations ping-pong
__device__ __align__(16) float g_c1[GC * NRC * 28];   // (g, r, k, m)

// ---------------- helpers ----------------
__device__ __forceinline__ float elu1(float x) { return x > 0.f ? x : expm1f(x); }

__device__ __forceinline__ void make_tables(int tid, float* sBc, float* sBs) {
    if (tid < NGRIDC) {
        float th = (float)tid * (TWO_PI_F / NGRIDC);
#pragma unroll
        for (int l = 0; l < 3; l++) {
            float s, c;
            sincosf((float)(l + 1) * th, &s, &c);
            sBc[tid * 3 + l] = c;
            sBs[tid * 3 + l] = s;
        }
    }
}

// project to 16 angular grid pts, ELU, project back
__device__ __forceinline__ void felu(
    float y0, const float yc[3], const float ys[3],
    const float* __restrict__ sBc, const float* __restrict__ sBs,
    float& z0, float zc[3], float zs[3])
{
    z0 = 0.f; zc[0] = zc[1] = zc[2] = 0.f; zs[0] = zs[1] = zs[2] = 0.f;
#pragma unroll
    for (int j = 0; j < NGRIDC; j++) {
        float c0 = sBc[j*3], c1v = sBc[j*3+1], c2v = sBc[j*3+2];
        float s0 = sBs[j*3], s1v = sBs[j*3+1], s2v = sBs[j*3+2];
        float v = y0 + yc[0]*c0 + yc[1]*c1v + yc[2]*c2v
                     + ys[0]*s0 + ys[1]*s1v + ys[2]*s2v;
        float w = elu1(v);
        z0 += w;
        zc[0] += w*c0; zc[1] += w*c1v; zc[2] += w*c2v;
        zs[0] += w*s0; zs[1] += w*s1v; zs[2] += w*s2v;
    }
    z0 *= (1.f/NGRIDC);
#pragma unroll
    for (int l = 0; l < 3; l++) { zc[l] *= (2.f/NGRIDC); zs[l] *= (2.f/NGRIDC); }
}

// ---------------- layer 1: matvec shared across actions within a batch elem ----
// grid (16, 2): (o-tile of 16, b). 256 threads, 8 warps, warp -> 2 o's.
__global__ __launch_bounds__(256, 1) void k_l1(
    const float* __restrict__ obs, const float* __restrict__ act,
    const float* __restrict__ W01, const float* __restrict__ b01,
    const float* __restrict__ AB1)
{
    const int tid = threadIdx.x, lane = tid & 31, wid = tid >> 5;
    const int bx = blockIdx.x, b = blockIdx.y;
    __shared__ float Xs[7 * 128];      // [comp][c]
    __shared__ float sY[16][7];
    __shared__ float sBc[48], sBs[48];

    const float* orow = obs + (size_t)b * (OBS_C * MC);
    for (int idx = tid; idx < OBS_C * MC; idx += 256) {
        int c = idx / 7, t = idx - c * 7;
        Xs[t * 128 + c] = orow[idx];
    }
    make_tables(tid, sBc, sBs);
    __syncthreads();

    const float4* Xs4 = (const float4*)Xs;
#pragma unroll
    for (int s = 0; s < 2; s++) {
        const int o = bx * 16 + wid * 2 + s;
        float acc[7];
#pragma unroll
        for (int m = 0; m < 7; m++) acc[m] = 0.f;

        const float* w0r = W01 + (size_t)o * (OBS_C + 1) + 4 * lane;
        float w0x = w0r[0], w0y = w0r[1], w0z = w0r[2], w0w = w0r[3];
        float4 v0 = Xs4[lane];
        acc[0] += w0x*v0.x + w0y*v0.y + w0z*v0.z + w0w*v0.w;
#pragma unroll
        for (int l = 0; l < 3; l++) {
            float4 a4 = ((const float4*)AB1)[((size_t)(2*l)*256 + o)*32 + lane];
            float4 b4 = ((const float4*)AB1)[((size_t)(2*l+1)*256 + o)*32 + lane];
            float4 vc = Xs4[(1 + 2*l)*32 + lane];
            float4 vs = Xs4[(2 + 2*l)*32 + lane];
            acc[1+2*l] += a4.x*vc.x - b4.x*vs.x;  acc[1+2*l] += a4.y*vc.y - b4.y*vs.y;
            acc[1+2*l] += a4.z*vc.z - b4.z*vs.z;  acc[1+2*l] += a4.w*vc.w - b4.w*vs.w;
            acc[2+2*l] += b4.x*vc.x + a4.x*vs.x;  acc[2+2*l] += b4.y*vc.y + a4.y*vs.y;
            acc[2+2*l] += b4.z*vc.z + a4.z*vs.z;  acc[2+2*l] += b4.w*vc.w + a4.w*vs.w;
        }
#pragma unroll
        for (int off = 16; off > 0; off >>= 1)
#pragma unroll
            for (int m = 0; m < 7; m++)
                acc[m] += __shfl_xor_sync(0xffffffffu, acc[m], off);
        if (lane == 0)
#pragma unroll
            for (int m = 0; m < 7; m++) sY[wid*2 + s][m] = acc[m];
    }
    __syncthreads();

    // activation: 16 o x 32 a = 512 items, 2 per thread; lane dim = o for coalesced writes
#pragma unroll
    for (int rep = 0; rep < 2; rep++) {
        const int a = rep * 16 + (tid >> 4);
        const int ol = tid & 15;
        const int o = bx * 16 + ol;
        const int g = b * 32 + a;
        float y0 = sY[ol][0] + b01[o] + W01[(size_t)o * 129 + 128] * act[g];
        float yc[3], ys[3];
#pragma unroll
        for (int l = 0; l < 3; l++) { yc[l] = sY[ol][1+2*l]; ys[l] = sY[ol][2+2*l]; }
        float z0, zc[3], zs[3];
        felu(y0, yc, ys, sBc, sBs, z0, zc, zs);
        float* xo = g_X[0] + (size_t)g * XSTR;
        xo[o] = z0;
#pragma unroll
        for (int l = 0; l < 3; l++) {
            xo[(1+2*l)*256 + o] = zc[l];
            xo[(2+2*l)*256 + o] = zs[l];
        }
    }
}

// ---------------- hidden layer: g-batched GEMM-style ----------------
// grid (16, 16): (o-tile of 16, g-tile of 4). warp -> 2 o's x 4 g's.
__global__ __launch_bounds__(256, 1) void k_hidden(
    const float* __restrict__ W0h, const float* __restrict__ b0h,
    const float* __restrict__ ABh, int layer, int inb)
{
    const int tid = threadIdx.x, lane = tid & 31, wid = tid >> 5;
    const int bx = blockIdx.x, gt = blockIdx.y;
    __shared__ float Xs[4 * XSTR];     // 28 KB: [g][comp][k]
    __shared__ float sY[16][4][7];
    __shared__ float sBc[48], sBs[48];

    {
        const float4* src = (const float4*)(g_X[inb] + (size_t)gt * 4 * XSTR);
        float4* dst = (float4*)Xs;
#pragma unroll
        for (int i = tid; i < 4 * XSTR / 4; i += 256) dst[i] = src[i];
    }
    make_tables(tid, sBc, sBs);
    __syncthreads();

    const float4* W04 = (const float4*)(W0h + (size_t)layer * 65536);
    const float4* AB4 = (const float4*)(ABh + (size_t)layer * 393216);
    const float4* Xs4 = (const float4*)Xs;

#pragma unroll
    for (int s = 0; s < 2; s++) {
        const int o = bx * 16 + wid * 2 + s;
        float acc[4][7];
#pragma unroll
        for (int g = 0; g < 4; g++)
#pragma unroll
            for (int m = 0; m < 7; m++) acc[g][m] = 0.f;

#pragma unroll
        for (int j = 0; j < 2; j++) {
            const int i4 = lane + 32 * j;
            float4 w0  = W04[(size_t)o * 64 + i4];
            float4 a0  = AB4[((size_t)0*256 + o)*64 + i4];
            float4 bb0 = AB4[((size_t)1*256 + o)*64 + i4];
            float4 a1  = AB4[((size_t)2*256 + o)*64 + i4];
            float4 bb1 = AB4[((size_t)3*256 + o)*64 + i4];
            float4 a2  = AB4[((size_t)4*256 + o)*64 + i4];
            float4 bb2 = AB4[((size_t)5*256 + o)*64 + i4];
#pragma unroll
            for (int g = 0; g < 4; g++) {
                const int base = g * (XSTR/4);
                float4 v0 = Xs4[base + i4];
                acc[g][0] += w0.x*v0.x + w0.y*v0.y + w0.z*v0.z + w0.w*v0.w;
                {
                    float4 vc = Xs4[base + 1*64 + i4];
                    float4 vs = Xs4[base + 2*64 + i4];
                    acc[g][1] += a0.x*vc.x - bb0.x*vs.x;  acc[g][1] += a0.y*vc.y - bb0.y*vs.y;
                    acc[g][1] += a0.z*vc.z - bb0.z*vs.z;  acc[g][1] += a0.w*vc.w - bb0.w*vs.w;
                    acc[g][2] += bb0.x*vc.x + a0.x*vs.x;  acc[g][2] += bb0.y*vc.y + a0.y*vs.y;
                    acc[g][2] += bb0.z*vc.z + a0.z*vs.z;  acc[g][2] += bb0.w*vc.w + a0.w*vs.w;
                }
                {
                    float4 vc = Xs4[base + 3*64 + i4];
                    float4 vs = Xs4[base + 4*64 + i4];
                    acc[g][3] += a1.x*vc.x - bb1.x*vs.x;  acc[g][3] += a1.y*vc.y - bb1.y*vs.y;
                    acc[g][3] += a1.z*vc.z - bb1.z*vs.z;  acc[g][3] += a1.w*vc.w - bb1.w*vs.w;
                    acc[g][4] += bb1.x*vc.x + a1.x*vs.x;  acc[g][4] += bb1.y*vc.y + a1.y*vs.y;
                    acc[g][4] += bb1.z*vc.z + a1.z*vs.z;  acc[g][4] += bb1.w*vc.w + a1.w*vs.w;
                }
                {
                    float4 vc = Xs4[base + 5*64 + i4];
                    float4 vs = Xs4[base + 6*64 + i4];
                    acc[g][5] += a2.x*vc.x - bb2.x*vs.x;  acc[g][5] += a2.y*vc.y - bb2.y*vs.y;
                    acc[g][5] += a2.z*vc.z - bb2.z*vs.z;  acc[g][5] += a2.w*vc.w - bb2.w*vs.w;
                    acc[g][6] += bb2.x*vc.x + a2.x*vs.x;  acc[g][6] += bb2.y*vc.y + a2.y*vs.y;
                    acc[g][6] += bb2.z*vc.z + a2.z*vs.z;  acc[g][6] += bb2.w*vc.w + a2.w*vs.w;
                }
            }
        }
#pragma unroll
        for (int off = 16; off > 0; off >>= 1)
#pragma unroll
            for (int g = 0; g < 4; g++)
#pragma unroll
                for (int m = 0; m < 7; m++)
                    acc[g][m] += __shfl_xor_sync(0xffffffffu, acc[g][m], off);
        if (lane == 0)
#pragma unroll
            for (int g = 0; g < 4; g++)
#pragma unroll
                for (int m = 0; m < 7; m++) sY[wid*2 + s][g][m] = acc[g][m];
    }
    __syncthreads();

    // activation: 16 o x 4 g = 64 items; lane dim = o
    if (tid < 64) {
        const int gl = tid >> 4, ol = tid & 15;
        const int o = bx * 16 + ol;
        const int g = gt * 4 + gl;
        float y0 = sY[ol][gl][0] + b0h[layer * 256 + o];
        float yc[3], ys[3];
#pragma unroll
        for (int l = 0; l < 3; l++) { yc[l] = sY[ol][gl][1+2*l]; ys[l] = sY[ol][gl][2+2*l]; }
        float z0, zc[3], zs[3];
        felu(y0, yc, ys, sBc, sBs, z0, zc, zs);
        float* xo = g_X[inb ^ 1] + (size_t)g * XSTR;
        xo[o] = z0;
#pragma unroll
        for (int l = 0; l < 3; l++) {
            xo[(1+2*l)*256 + o] = zc[l];
            xo[(2+2*l)*256 + o] = zs[l];
        }
    }
}

// ---------------- output layer + radial contraction ----------------
// grid 64 (per g), 256 threads.
__global__ __launch_bounds__(256, 1) void k_out(
    const float* __restrict__ Wout, const float* __restrict__ bout,
    const float* __restrict__ ABout, const float* __restrict__ rad, int inb)
{
    const int tid = threadIdx.x, lane = tid & 31, wid = tid >> 5;
    const int g = blockIdx.x;
    __shared__ float Xs[XSTR];
    __shared__ float sC[16][7];

    {
        const float4* src = (const float4*)(g_X[inb] + (size_t)g * XSTR);
        float4* dst = (float4*)Xs;
#pragma unroll
        for (int i = tid; i < XSTR/4; i += 256) dst[i] = src[i];
    }
    __syncthreads();

    const float4* Xs4 = (const float4*)Xs;
#pragma unroll
    for (int s = 0; s < 2; s++) {
        const int o = wid * 2 + s;
        float acc[7];
#pragma unroll
        for (int m = 0; m < 7; m++) acc[m] = 0.f;
#pragma unroll
        for (int j = 0; j < 2; j++) {
            const int i4 = lane + 32 * j;
            float4 w0 = ((const float4*)Wout)[(size_t)o * 64 + i4];
            float4 v0 = Xs4[i4];
            acc[0] += w0.x*v0.x + w0.y*v0.y + w0.z*v0.z + w0.w*v0.w;
#pragma unroll
            for (int l = 0; l < 3; l++) {
                float4 a4 = ((const float4*)ABout)[((size_t)(2*l)*16 + o)*64 + i4];
                float4 b4 = ((const float4*)ABout)[((size_t)(2*l+1)*16 + o)*64 + i4];
                float4 vc = Xs4[(1+2*l)*64 + i4];
                float4 vs = Xs4[(2+2*l)*64 + i4];
                acc[1+2*l] += a4.x*vc.x - b4.x*vs.x;  acc[1+2*l] += a4.y*vc.y - b4.y*vs.y;
                acc[1+2*l] += a4.z*vc.z - b4.z*vs.z;  acc[1+2*l] += a4.w*vc.w - b4.w*vs.w;
                acc[2+2*l] += b4.x*vc.x + a4.x*vs.x;  acc[2+2*l] += b4.y*vc.y + a4.y*vs.y;
                acc[2+2*l] += b4.z*vc.z + a4.z*vs.z;  acc[2+2*l] += b4.w*vc.w + a4.w*vs.w;
            }
        }
#pragma unroll
        for (int off = 16; off > 0; off >>= 1)
#pragma unroll
            for (int m = 0; m < 7; m++)
                acc[m] += __shfl_xor_sync(0xffffffffu, acc[m], off);
        if (lane == 0) {
            sC[o][0] = acc[0] + bout[o];
#pragma unroll
            for (int m = 1; m < 7; m++) sC[o][m] = acc[m];
        }
    }
    __syncthreads();

    // radial: c1[g,r,k,m] = sum_n coeffs[n*4+k][m] * rad[m][n][r]
    const int k = tid >> 6, r = tid & 63;
    float* dst = g_c1 + ((size_t)(g * NRC + r)) * 28 + k * MC;
#pragma unroll
    for (int m = 0; m < MC; m++) {
        float s = 0.f;
#pragma unroll
        for (int n = 0; n < 4; n++)
            s += sC[n*4 + k][m] * rad[(m*4 + n) * NRC + r];
        dst[m] = s;
    }
}

// ---------------- expansion kernel (HBM-write bound) ----------------
__global__ __launch_bounds__(256) void k_expand(float* __restrict__ out)
{
    const int gr = blockIdx.x;          // g*NR + r
    const int tid = threadIdx.x;
    __shared__ float sc1[28];
    __shared__ float su[NPC * 4];       // [p][k] -> float4 per p
    __shared__ float sax[NHC * 4];      // [h][k] -> float4 per h

    if (tid < 28) sc1[tid] = g_c1[(size_t)gr * 28 + tid];
    {
        int h = tid >> 2, k = tid & 3;
        sax[tid] = 1.4142135623730951f *
                   sinf((float)(k + 1) * PI_F * (float)h * (1.f / (NHC - 1)));
    }
    __syncthreads();

    const float A0 = 0.3989422804014327f;   // 1/sqrt(2*pi)
    const float ISP = 0.5641895835477563f;  // 1/sqrt(pi)
#pragma unroll
    for (int idx = tid; idx < 512; idx += 256) {
        int k = idx >> 7, p = idx & 127;
        float phi = (float)p * (TWO_PI_F / NPC);
        float s1, c1v;
        sincosf(phi, &s1, &c1v);
        float c2v = c1v*c1v - s1*s1;
        float s2  = 2.f*s1*c1v;
        float c3v = c2v*c1v - s2*s1;
        float s3  = s2*c1v + c2v*s1;
        const float* c = sc1 + k * MC;
        su[p * 4 + k] = c[0]*A0 + ISP*(c[1]*c1v + c[2]*s1 +
                                       c[3]*c2v + c[4]*s2 +
                                       c[5]*c3v + c[6]*s3);
    }
    const int hgrp = tid & 15;
    float4 axj[4];
#pragma unroll
    for (int j = 0; j < 4; j++)
        axj[j] = ((const float4*)sax)[hgrp * 4 + j];
    __syncthreads();

    const float4* su4 = (const float4*)su;
    float4* ob = (float4*)out + (size_t)gr * (NPC * NHC / 4);
    const int pg = tid >> 4;
#pragma unroll
    for (int it = 0; it < 8; it++) {
        int p = it * 16 + pg;
        float4 u = su4[p];
        float4 v;
        v.x = u.x*axj[0].x + u.y*axj[0].y + u.z*axj[0].z + u.w*axj[0].w;
        v.y = u.x*axj[1].x + u.y*axj[1].y + u.z*axj[1].z + u.w*axj[1].w;
        v.z = u.x*axj[2].x + u.y*axj[2].y + u.z*axj[2].z + u.w*axj[2].w;
        v.w = u.x*axj[3].x + u.y*axj[3].y + u.z*axj[3].z + u.w*axj[3].w;
        __stcs(&ob[p * 16 + hgrp], v);
    }
}

// ---------------- launch ----------------
extern "C" void kernel_launch(void* const* d_in, const int* in_sizes, int n_in,
                              void* d_out, int out_size)
{
    const float* obs   = (const float*)d_in[0];
    const float* act   = (const float*)d_in[1];
    const float* W0_1  = (const float*)d_in[2];
    const float* b0_1  = (const float*)d_in[3];
    const float* AB1   = (const float*)d_in[4];
    const float* W0_h  = (const float*)d_in[5];
    const float* b0_h  = (const float*)d_in[6];
    const float* ABh   = (const float*)d_in[7];
    const float* Wout0 = (const float*)d_in[8];
    const float* bout0 = (const float*)d_in[9];
    const float* ABout = (const float*)d_in[10];
    const float* rad   = (const float*)d_in[11];

    k_l1<<<dim3(16, 2), 256>>>(obs, act, W0_1, b0_1, AB1);
    k_hidden<<<dim3(16, 16), 256>>>(W0_h, b0_h, ABh, 0, 0);
    k_hidden<<<dim3(16, 16), 256>>>(W0_h, b0_h, ABh, 1, 1);
    k_out<<<64, 256>>>(Wout0, bout0, ABout, rad, 0);
    k_expand<<<GC * NRC, 256>>>((float*)d_out);
}